// round 4
// baseline (speedup 1.0000x reference)
#include <cuda_runtime.h>
#include <cuda_bf16.h>
#include <cstdint>

// Problem constants (match reference)
#define NUM_TABLES 26
#define NUM_EMB    100000
#define EMB_DIM    64
#define DENSE_DIM  512
#define BATCH      4096
#define BAG        50
#define HIDDEN_OUT 512
#define FEAT_DIM   (NUM_TABLES * EMB_DIM + EMB_DIM)   // 1728

// Scratch (device globals — no allocation allowed)
__device__ __align__(256) float g_H1[BATCH * DENSE_DIM];     // dense hidden    (8 MB)
__device__ __align__(256) float g_FEAT[BATCH * FEAT_DIM];    // concat features (28.3 MB)
__device__ __align__(256) float g_H2[BATCH * HIDDEN_OUT];    // output hidden   (8 MB)
__device__ int g_idx_is64;                                   // index dtype flag

// ---------------------------------------------------------------------------
// Index dtype detection: indices are < 100000, so an int64 (LE) buffer has
// all-zero odd 32-bit words. For real int32 index data the OR of 256 random
// words in [0,100000) is ~never zero. Single thread, negligible cost.
// ---------------------------------------------------------------------------
__global__ void detect_idx_dtype_kernel(const int* __restrict__ idx)
{
    int o = 0;
    #pragma unroll 8
    for (int i = 1; i < 512; i += 2) o |= idx[i];
    g_idx_is64 = (o == 0) ? 1 : 0;
}

// ---------------------------------------------------------------------------
// GEMM: C[m,n] = relu( sum_k A[m,k] * B[n,k] + bias[n] )
// A: [M,K] row-major (row stride == K), B: [N,K] row-major, C row stride ldc.
// Requires M%BM==0, N%BN==0, K%BK==0, BK%4==0, TN==4 (float4 epilogue).
// ---------------------------------------------------------------------------
template<int BM, int BN, int BK, int TM, int TN>
__global__ __launch_bounds__((BM/TM)*(BN/TN))
void gemm_bt_bias_relu(const float* __restrict__ A,
                       const float* __restrict__ B,
                       const float* __restrict__ bias,
                       float* __restrict__ C,
                       int K, int ldc)
{
    constexpr int THREADS = (BM/TM)*(BN/TN);
    __shared__ __align__(16) float As[BK][BM];
    __shared__ __align__(16) float Bs[BK][BN];

    const int tid = threadIdx.x;
    const int tx  = tid % (BN/TN);
    const int ty  = tid / (BN/TN);
    const int bm0 = blockIdx.y * BM;
    const int bn0 = blockIdx.x * BN;

    float acc[TM][TN];
    #pragma unroll
    for (int i = 0; i < TM; i++)
        #pragma unroll
        for (int j = 0; j < TN; j++) acc[i][j] = 0.f;

    for (int k0 = 0; k0 < K; k0 += BK) {
        // Load A tile (transpose to k-major smem)
        #pragma unroll
        for (int i = tid; i < BM*BK/4; i += THREADS) {
            int row = (i*4) / BK;
            int kk  = (i*4) % BK;
            float4 v = *(const float4*)(A + (size_t)(bm0 + row) * K + k0 + kk);
            As[kk+0][row] = v.x; As[kk+1][row] = v.y;
            As[kk+2][row] = v.z; As[kk+3][row] = v.w;
        }
        // Load B tile (transpose to k-major smem)
        #pragma unroll
        for (int i = tid; i < BN*BK/4; i += THREADS) {
            int row = (i*4) / BK;
            int kk  = (i*4) % BK;
            float4 v = *(const float4*)(B + (size_t)(bn0 + row) * K + k0 + kk);
            Bs[kk+0][row] = v.x; Bs[kk+1][row] = v.y;
            Bs[kk+2][row] = v.z; Bs[kk+3][row] = v.w;
        }
        __syncthreads();

        #pragma unroll
        for (int k = 0; k < BK; k++) {
            float a[TM], b[TN];
            #pragma unroll
            for (int i = 0; i < TM; i += 4) {
                float4 v = *(const float4*)&As[k][ty*TM + i];
                a[i+0] = v.x; a[i+1] = v.y; a[i+2] = v.z; a[i+3] = v.w;
            }
            #pragma unroll
            for (int j = 0; j < TN; j += 4) {
                float4 v = *(const float4*)&Bs[k][tx*TN + j];
                b[j+0] = v.x; b[j+1] = v.y; b[j+2] = v.z; b[j+3] = v.w;
            }
            #pragma unroll
            for (int i = 0; i < TM; i++)
                #pragma unroll
                for (int j = 0; j < TN; j++)
                    acc[i][j] = fmaf(a[i], b[j], acc[i][j]);
        }
        __syncthreads();
    }

    // Epilogue: bias + relu, float4 stores (TN==4)
    #pragma unroll
    for (int i = 0; i < TM; i++) {
        int row = bm0 + ty*TM + i;
        int col = bn0 + tx*TN;
        float4 o;
        o.x = fmaxf(acc[i][0] + bias[col+0], 0.f);
        o.y = fmaxf(acc[i][1] + bias[col+1], 0.f);
        o.z = fmaxf(acc[i][2] + bias[col+2], 0.f);
        o.w = fmaxf(acc[i][3] + bias[col+3], 0.f);
        *(float4*)(C + (size_t)row * ldc + col) = o;
    }
}

// ---------------------------------------------------------------------------
// Embedding bag pooling: one warp per (table, batch) bag.
// Index dtype (int32 vs int64) selected at runtime via g_idx_is64 (uniform
// branch). Indices clamped to [0, NUM_EMB) so any surprise becomes a visible
// wrong answer, never an OOB crash.
// Lane handles dims [2*lane, 2*lane+1] (float2). Indices loaded in chunks of
// 10 to expose memory-level parallelism on the gather loads.
// Table-major bag order -> consecutive blocks hit the same 25.6 MB table.
// ---------------------------------------------------------------------------
__global__ __launch_bounds__(256)
void emb_pool_kernel(const int* __restrict__ idx,
                     const float* __restrict__ tables,
                     float* __restrict__ feat)
{
    const int bag  = blockIdx.x * (blockDim.x >> 5) + (threadIdx.x >> 5);
    if (bag >= NUM_TABLES * BATCH) return;
    const int t    = bag / BATCH;
    const int b    = bag % BATCH;
    const int lane = threadIdx.x & 31;
    const int is64 = g_idx_is64;

    const size_t bag_off = ((size_t)t * BATCH + b) * BAG;
    const float* tbl = tables + (size_t)t * NUM_EMB * EMB_DIM;

    float2 acc = make_float2(0.f, 0.f);
    #pragma unroll
    for (int l0 = 0; l0 < BAG; l0 += 10) {
        int ids[10];
        if (is64) {
            const long long* ip = (const long long*)idx + bag_off + l0;
            #pragma unroll
            for (int j = 0; j < 10; j++) ids[j] = (int)__ldg(&ip[j]);
        } else {
            const int* ip = idx + bag_off + l0;
            #pragma unroll
            for (int j = 0; j < 10; j++) ids[j] = __ldg(&ip[j]);
        }
        #pragma unroll
        for (int j = 0; j < 10; j++) {
            int id = min(max(ids[j], 0), NUM_EMB - 1);
            const float2* row = (const float2*)(tbl + (size_t)id * EMB_DIM);
            float2 v = __ldg(&row[lane]);
            acc.x += v.x; acc.y += v.y;
        }
    }
    float* out = feat + (size_t)b * FEAT_DIM + EMB_DIM + (size_t)t * EMB_DIM;
    ((float2*)out)[lane] = acc;
}

// ---------------------------------------------------------------------------
// Final layer: logits[b] = relu( dot(H2[b,:], w2[:]) + b2 ). One warp per row.
// ---------------------------------------------------------------------------
__global__ __launch_bounds__(256)
void out_final_kernel(const float* __restrict__ H2,
                      const float* __restrict__ w2,
                      const float* __restrict__ b2,
                      float* __restrict__ out)
{
    const int warp = (blockIdx.x * blockDim.x + threadIdx.x) >> 5;
    const int lane = threadIdx.x & 31;
    if (warp >= BATCH) return;

    const float4* h4 = (const float4*)(H2 + (size_t)warp * HIDDEN_OUT);
    const float4* w4 = (const float4*)w2;
    float s = 0.f;
    #pragma unroll
    for (int i = 0; i < HIDDEN_OUT/4/32; i++) {   // 4 iterations
        float4 h = h4[lane + i*32];
        float4 w = __ldg(&w4[lane + i*32]);
        s = fmaf(h.x, w.x, s); s = fmaf(h.y, w.y, s);
        s = fmaf(h.z, w.z, s); s = fmaf(h.w, w.w, s);
    }
    #pragma unroll
    for (int o = 16; o; o >>= 1) s += __shfl_xor_sync(0xFFFFFFFFu, s, o);
    if (lane == 0) out[warp] = fmaxf(s + b2[0], 0.f);
}

// ---------------------------------------------------------------------------
// Launch. Symbol addresses resolved once (host statics) so the captured graph
// body is kernel launches only.
// ---------------------------------------------------------------------------
extern "C" void kernel_launch(void* const* d_in, const int* in_sizes, int n_in,
                              void* d_out, int out_size)
{
    const float* dense = (const float*)d_in[0];       // [4096, 512]
    const int*   sidx  = (const int*)d_in[1];         // [26, 4096, 50] int32 or int64
    const float* emb   = (const float*)d_in[2];       // [26, 100000, 64]
    const float* d_w1  = (const float*)d_in[3];       // [512, 512]
    const float* d_b1  = (const float*)d_in[4];       // [512]
    const float* d_w2  = (const float*)d_in[5];       // [64, 512]
    const float* d_b2  = (const float*)d_in[6];       // [64]
    const float* o_w1  = (const float*)d_in[7];       // [512, 1728]
    const float* o_b1  = (const float*)d_in[8];       // [512]
    const float* o_w2  = (const float*)d_in[9];       // [1, 512]
    const float* o_b2  = (const float*)d_in[10];      // [1]
    float* out = (float*)d_out;                       // [4096, 1]

    static float* H1   = nullptr;
    static float* FEAT = nullptr;
    static float* H2   = nullptr;
    if (!H1) {
        cudaGetSymbolAddress((void**)&H1,   g_H1);
        cudaGetSymbolAddress((void**)&FEAT, g_FEAT);
        cudaGetSymbolAddress((void**)&H2,   g_H2);
    }

    // 0) index dtype detection (device-side, graph-capturable)
    detect_idx_dtype_kernel<<<1, 1>>>(sidx);

    // 1) dense MLP layer 1: [4096,512] @ [512,512]^T -> H1 (relu)
    {
        dim3 grid(DENSE_DIM/64, BATCH/128);
        gemm_bt_bias_relu<128,64,16,8,4><<<grid, 256>>>(dense, d_w1, d_b1, H1,
                                                        DENSE_DIM, DENSE_DIM);
    }
    // 2) embedding pooling -> FEAT columns [64, 1728)
    {
        int bags = NUM_TABLES * BATCH;
        int blocks = (bags + 7) / 8;
        emb_pool_kernel<<<blocks, 256>>>(sidx, emb, FEAT);
    }
    // 3) dense MLP layer 2: H1 @ [64,512]^T -> FEAT columns [0,64) (relu)
    {
        dim3 grid(EMB_DIM/64, BATCH/64);
        gemm_bt_bias_relu<64,64,16,4,4><<<grid, 256>>>(H1, d_w2, d_b2, FEAT,
                                                       DENSE_DIM, FEAT_DIM);
    }
    // 4) output MLP layer 1: FEAT[4096,1728] @ [512,1728]^T -> H2 (relu)
    {
        dim3 grid(HIDDEN_OUT/64, BATCH/128);
        gemm_bt_bias_relu<128,64,16,8,4><<<grid, 256>>>(FEAT, o_w1, o_b1, H2,
                                                        FEAT_DIM, HIDDEN_OUT);
    }
    // 5) output MLP layer 2: dot + relu -> out
    {
        out_final_kernel<<<(BATCH*32)/256, 256>>>(H2, o_w2, o_b2, out);
    }
}